// round 7
// baseline (speedup 1.0000x reference)
#include <cuda_runtime.h>
#include <cuda_bf16.h>
#include <cstdint>
#include <math.h>

// ---------------- problem constants ----------------
#define BB    2
#define TT    2048
#define EE    1024
#define HH    16
#define HD    64
#define FFD   4096
#define MT    (BB*TT)        // 4096 tokens

// ---------------- scratch (device globals) -------------------------------
__device__ __align__(16) float g_x1[MT*EE];

__device__ __align__(16) __nv_bfloat16 g_aHi [MT*EE];
__device__ __align__(16) __nv_bfloat16 g_aLo [MT*EE];
__device__ __align__(16) __nv_bfloat16 g_qHi [MT*EE];
__device__ __align__(16) __nv_bfloat16 g_qLo [MT*EE];
__device__ __align__(16) __nv_bfloat16 g_kHi [MT*EE];
__device__ __align__(16) __nv_bfloat16 g_kLo [MT*EE];
__device__ __align__(16) __nv_bfloat16 g_vtHi[EE*MT];
__device__ __align__(16) __nv_bfloat16 g_vtLo[EE*MT];
__device__ __align__(16) __nv_bfloat16 g_atHi[MT*EE];
__device__ __align__(16) __nv_bfloat16 g_atLo[MT*EE];
__device__ __align__(16) __nv_bfloat16 g_ffHi[MT*FFD];
__device__ __align__(16) __nv_bfloat16 g_ffLo[MT*FFD];
__device__ __align__(16) __nv_bfloat16 g_wHi [12582912];
__device__ __align__(16) __nv_bfloat16 g_wLo [12582912];

#define WQ_OFF 0
#define WK_OFF 1048576
#define WV_OFF 2097152
#define WO_OFF 3145728
#define W1_OFF 4194304
#define W2_OFF 8388608

// ================= helpers ================================================
__device__ __forceinline__ uint32_t smem_u32(const void* p) {
    uint32_t a;
    asm("{ .reg .u64 t; cvta.to.shared.u64 t, %1; cvt.u32.u64 %0, t; }"
        : "=r"(a) : "l"(p));
    return a;
}
__device__ __forceinline__ void cp16(uint32_t dst, const void* src) {
    asm volatile("cp.async.cg.shared.global [%0], [%1], 16;"
                 :: "r"(dst), "l"(src));
}
__device__ __forceinline__ void cp_commit() {
    asm volatile("cp.async.commit_group;" ::: "memory");
}
__device__ __forceinline__ void cp_wait1() {
    asm volatile("cp.async.wait_group 1;" ::: "memory");
}
__device__ __forceinline__ void mma16816(float* d, const uint32_t* a,
                                         const uint32_t* b) {
    asm volatile(
        "mma.sync.aligned.m16n8k16.row.col.f32.bf16.bf16.f32 "
        "{%0,%1,%2,%3}, {%4,%5,%6,%7}, {%8,%9}, {%0,%1,%2,%3};"
        : "+f"(d[0]), "+f"(d[1]), "+f"(d[2]), "+f"(d[3])
        : "r"(a[0]), "r"(a[1]), "r"(a[2]), "r"(a[3]), "r"(b[0]), "r"(b[1]));
}
__device__ __forceinline__ void ldsm4(uint32_t* r, uint32_t addr) {
    asm volatile("ldmatrix.sync.aligned.m8n8.x4.shared.b16 {%0,%1,%2,%3}, [%4];"
        : "=r"(r[0]), "=r"(r[1]), "=r"(r[2]), "=r"(r[3]) : "r"(addr));
}
// exp(x) for x <= 0, FMA-pipe only (no MUFU). rel err ~2e-6.
__device__ __forceinline__ float fast_exp(float x) {
    x = fmaxf(x, -80.0f);
    const float z = x * 1.4426950408889634f;
    const float t = z + 12582912.0f;
    const int  ik = __float_as_int(t) - 0x4B400000;
    const float f = z - (t - 12582912.0f);
    float p = 1.3333558146e-3f;
    p = fmaf(p, f, 9.6181291071e-3f);
    p = fmaf(p, f, 5.5504108664e-2f);
    p = fmaf(p, f, 2.4022650696e-1f);
    p = fmaf(p, f, 6.9314718056e-1f);
    p = fmaf(p, f, 1.0f);
    return __int_as_float(__float_as_int(p) + (ik << 23));
}
__device__ __forceinline__ void split2(float x, float y, uint32_t& hi, uint32_t& lo) {
    __nv_bfloat162 hp = __floats2bfloat162_rn(x, y);
    hi = *reinterpret_cast<uint32_t*>(&hp);
    __nv_bfloat162 lp = __floats2bfloat162_rn(x - __bfloat162float(hp.x),
                                              y - __bfloat162float(hp.y));
    lo = *reinterpret_cast<uint32_t*>(&lp);
}

// ================= LayerNorm -> bf16 hi/lo ===============================
__global__ void ln_kernel(const float* __restrict__ x,
                          const float* __restrict__ gw,
                          const float* __restrict__ bw,
                          __nv_bfloat16* __restrict__ hi,
                          __nv_bfloat16* __restrict__ lo)
{
    const int row = blockIdx.x;
    const int tid = threadIdx.x;
    const float4 xv = ((const float4*)(x + (size_t)row * EE))[tid];

    float s  = xv.x + xv.y + xv.z + xv.w;
    float ss = xv.x*xv.x + xv.y*xv.y + xv.z*xv.z + xv.w*xv.w;
    #pragma unroll
    for (int off = 16; off; off >>= 1) {
        s  += __shfl_xor_sync(0xffffffffu, s,  off);
        ss += __shfl_xor_sync(0xffffffffu, ss, off);
    }
    __shared__ float as_[8], bs_[8];
    __shared__ float mu_s, inv_s;
    if ((tid & 31) == 0) { as_[tid >> 5] = s; bs_[tid >> 5] = ss; }
    __syncthreads();
    if (tid == 0) {
        float S = 0.f, SS = 0.f;
        #pragma unroll
        for (int i = 0; i < 8; i++) { S += as_[i]; SS += bs_[i]; }
        const float mu  = S * (1.0f / EE);
        const float var = SS * (1.0f / EE) - mu * mu;
        mu_s  = mu;
        inv_s = rsqrtf(var + 1e-5f);
    }
    __syncthreads();
    const float mu = mu_s, inv = inv_s;
    const float4 gv = ((const float4*)gw)[tid];
    const float4 bv = ((const float4*)bw)[tid];
    const float o0 = (xv.x - mu) * inv * gv.x + bv.x;
    const float o1 = (xv.y - mu) * inv * gv.y + bv.y;
    const float o2 = (xv.z - mu) * inv * gv.z + bv.z;
    const float o3 = (xv.w - mu) * inv * gv.w + bv.w;
    uint32_t h01, l01, h23, l23;
    split2(o0, o1, h01, l01);
    split2(o2, o3, h23, l23);
    ((uint2*)(hi + (size_t)row * EE))[tid] = make_uint2(h01, h23);
    ((uint2*)(lo + (size_t)row * EE))[tid] = make_uint2(l01, l23);
}

// ================= fused weight split =====================================
__global__ void wsplit_kernel(const float* __restrict__ Wq, const float* __restrict__ Wk,
                              const float* __restrict__ Wv, const float* __restrict__ Wo,
                              const float* __restrict__ W1, const float* __restrict__ W2,
                              __nv_bfloat16* __restrict__ hi,
                              __nv_bfloat16* __restrict__ lo)
{
    const int i = blockIdx.x * blockDim.x + threadIdx.x;   // < 3145728
    const float* src;
    int si;
    if (i < (1 << 20)) {
        const int w = i >> 18;
        src = (w == 0) ? Wq : (w == 1) ? Wk : (w == 2) ? Wv : Wo;
        si = i & ((1 << 18) - 1);
    } else {
        const int j = i - (1 << 20);
        if (j < (1 << 20)) { src = W1; si = j; }
        else               { src = W2; si = j - (1 << 20); }
    }
    const float4 v = ((const float4*)src)[si];
    uint32_t h01, l01, h23, l23;
    split2(v.x, v.y, h01, l01);
    split2(v.z, v.w, h23, l23);
    ((uint2*)hi)[i] = make_uint2(h01, h23);
    ((uint2*)lo)[i] = make_uint2(l01, l23);
}

// ================= mma.sync GEMM (512 thr, 16 warps, 1 sync/chunk) ========
// Y = A @ W^T (+bias)(+res)(relu)(*scale); OUT: 0 fp32, 1 bf16 split,
// 2 bf16 split transposed. CTA 128x128, BK=64, warp tile 32x32, 3 stages.
#define OPB   16384
#define STB   (4*OPB)
#define NSTG  3
#define GEMM_SMEM (NSTG*STB)      // 196608

__device__ __forceinline__ void gemm_ld_chunk(
    uint32_t smst,
    const __nv_bfloat16* __restrict__ Ahi, const __nv_bfloat16* __restrict__ Alo,
    const __nv_bfloat16* __restrict__ Bhi, const __nv_bfloat16* __restrict__ Blo,
    int bm, int bn, int K, int kc, int tid)
{
    #pragma unroll
    for (int i = 0; i < 8; i++) {
        const int f   = tid + (i << 9);
        const int op  = f >> 10;
        const int e   = f & 1023;
        const int row = e >> 3;
        const int c   = e & 7;
        const __nv_bfloat16* src;
        int rb;
        if (op == 0)      { src = Ahi; rb = bm; }
        else if (op == 1) { src = Alo; rb = bm; }
        else if (op == 2) { src = Bhi; rb = bn; }
        else              { src = Blo; rb = bn; }
        const void* g = src + (size_t)(rb + row) * K + kc * 64 + c * 8;
        const uint32_t d = smst + (op << 14) + (row << 7)
                         + ((c ^ (row & 7)) << 4);
        cp16(d, g);
    }
}

template<int RELU, int HASRES, int OUT>
__global__ void __launch_bounds__(512, 1)
mma_gemm_kernel(const __nv_bfloat16* __restrict__ Ahi,
                const __nv_bfloat16* __restrict__ Alo,
                const __nv_bfloat16* __restrict__ Bhi,
                const __nv_bfloat16* __restrict__ Blo,
                const float* __restrict__ bias,
                const float* __restrict__ res,
                float* __restrict__ Y,
                __nv_bfloat16* __restrict__ Yhi,
                __nv_bfloat16* __restrict__ Ylo,
                float scale, int M, int N, int K)
{
    extern __shared__ char smc[];
    const uint32_t smb = smem_u32(smc);
    const int tid  = threadIdx.x;
    const int wid  = tid >> 5;
    const int lane = tid & 31;
    const int g = lane >> 2, q = lane & 3;
    const int wm = wid & 3, wn = wid >> 2;       // 4x4 warp grid
    const int bm = blockIdx.y << 7;
    const int bn = blockIdx.x << 7;

    // ldmatrix lane addressing
    const int lrow = lane & 7;
    const int a_ch = (lane >> 4) & 1;    // A x4: matrices 0,1=ch0 rows r,r+8; 2,3=ch1
    const int b_ch = (lane >> 3) & 1;    // B x4: matrices 0,1=frag n (ch0,ch1); 2,3=frag n+8
    uint32_t arow[2], brow[2];
    #pragma unroll
    for (int mi = 0; mi < 2; mi++)
        arow[mi] = (uint32_t)(wm * 32 + mi * 16 + ((lane >> 3) & 1) * 8 + lrow) << 7;
    #pragma unroll
    for (int nj = 0; nj < 2; nj++)
        brow[nj] = (uint32_t)(wn * 32 + nj * 16 + ((lane >> 4) & 1) * 8 + lrow) << 7;

    float acc[2][4][4];
    #pragma unroll
    for (int mi = 0; mi < 2; mi++)
        #pragma unroll
        for (int ni = 0; ni < 4; ni++)
            #pragma unroll
            for (int r = 0; r < 4; r++) acc[mi][ni][r] = 0.0f;

    const int nk = K >> 6;
    gemm_ld_chunk(smb,       Ahi, Alo, Bhi, Blo, bm, bn, K, 0, tid);
    cp_commit();
    gemm_ld_chunk(smb + STB, Ahi, Alo, Bhi, Blo, bm, bn, K, 1, tid);
    cp_commit();

    for (int c = 0; c < nk; c++) {
        const int p  = c % 3;
        cp_wait1();
        __syncthreads();
        // issue next loads first (slot consumed at iter c-1; safe after the sync)
        if (c + 2 < nk)
            gemm_ld_chunk(smb + ((c + 2) % 3) * STB, Ahi, Alo, Bhi, Blo,
                          bm, bn, K, c + 2, tid);
        cp_commit();

        const uint32_t sb  = smb + p * STB;
        const uint32_t abh = sb;
        const uint32_t abl = sb + OPB;
        const uint32_t bbh = sb + 2 * OPB;
        const uint32_t bbl = sb + 3 * OPB;

        #pragma unroll
        for (int s = 0; s < 4; s++) {
            const uint32_t aswz = (uint32_t)(((2 * s + a_ch) ^ lrow) << 4);
            const uint32_t bswz = (uint32_t)(((2 * s + b_ch) ^ lrow) << 4);
            uint32_t ah[2][4], al[2][4], bh[2][4], bl[2][4];
            #pragma unroll
            for (int mi = 0; mi < 2; mi++) ldsm4(ah[mi], abh + arow[mi] + aswz);
            #pragma unroll
            for (int mi = 0; mi < 2; mi++) ldsm4(al[mi], abl + arow[mi] + aswz);
            #pragma unroll
            for (int nj = 0; nj < 2; nj++) ldsm4(bh[nj], bbh + brow[nj] + bswz);
            #pragma unroll
            for (int nj = 0; nj < 2; nj++) ldsm4(bl[nj], bbl + brow[nj] + bswz);
            #pragma unroll
            for (int mi = 0; mi < 2; mi++)
                #pragma unroll
                for (int ni = 0; ni < 4; ni++)
                    mma16816(acc[mi][ni], ah[mi], &bh[ni >> 1][(ni & 1) << 1]);
            #pragma unroll
            for (int mi = 0; mi < 2; mi++)
                #pragma unroll
                for (int ni = 0; ni < 4; ni++)
                    mma16816(acc[mi][ni], ah[mi], &bl[ni >> 1][(ni & 1) << 1]);
            #pragma unroll
            for (int mi = 0; mi < 2; mi++)
                #pragma unroll
                for (int ni = 0; ni < 4; ni++)
                    mma16816(acc[mi][ni], al[mi], &bh[ni >> 1][(ni & 1) << 1]);
        }
    }

    // ---- epilogue ----
    #pragma unroll
    for (int mi = 0; mi < 2; mi++) {
        #pragma unroll
        for (int ni = 0; ni < 4; ni++) {
            const int row0 = bm + wm * 32 + mi * 16 + g;
            const int col  = bn + wn * 32 + ni * 8 + q * 2;
            const float b0 = bias[col], b1 = bias[col + 1];
            float v0 = acc[mi][ni][0] + b0;
            float v1 = acc[mi][ni][1] + b1;
            float v2 = acc[mi][ni][2] + b0;
            float v3 = acc[mi][ni][3] + b1;
            if (HASRES) {
                const float2 r0 = *(const float2*)&res[(size_t)row0 * N + col];
                const float2 r1 = *(const float2*)&res[(size_t)(row0 + 8) * N + col];
                v0 += r0.x; v1 += r0.y; v2 += r1.x; v3 += r1.y;
            }
            if (RELU) {
                v0 = fmaxf(v0, 0.f); v1 = fmaxf(v1, 0.f);
                v2 = fmaxf(v2, 0.f); v3 = fmaxf(v3, 0.f);
            }
            if (OUT == 0) {
                *(float2*)&Y[(size_t)row0 * N + col]       = make_float2(v0, v1);
                *(float2*)&Y[(size_t)(row0 + 8) * N + col] = make_float2(v2, v3);
            } else {
                v0 *= scale; v1 *= scale; v2 *= scale; v3 *= scale;
                if (OUT == 1) {
                    uint32_t h, l;
                    split2(v0, v1, h, l);
                    *(uint32_t*)&Yhi[(size_t)row0 * N + col] = h;
                    *(uint32_t*)&Ylo[(size_t)row0 * N + col] = l;
                    split2(v2, v3, h, l);
                    *(uint32_t*)&Yhi[(size_t)(row0 + 8) * N + col] = h;
                    *(uint32_t*)&Ylo[(size_t)(row0 + 8) * N + col] = l;
                } else {   // transposed split (for V): vt[col][row]
                    #pragma unroll
                    for (int e = 0; e < 4; e++) {
                        const float v = (e == 0) ? v0 : (e == 1) ? v1 : (e == 2) ? v2 : v3;
                        const int cc = col + (e & 1);
                        const int rr = row0 + ((e >> 1) << 3);
                        const __nv_bfloat16 hv = __float2bfloat16(v);
                        const __nv_bfloat16 lv = __float2bfloat16(v - __bfloat162float(hv));
                        Yhi[(size_t)cc * M + rr] = hv;
                        Ylo[(size_t)cc * M + rr] = lv;
                    }
                }
            }
        }
    }
}

// ================= mma flash attention (unchanged from R6) ================
#define ATT_Q   32768
#define ATT_STG 32768
#define ATT_SMEM (ATT_Q + 2*ATT_STG)   // 98304

__global__ void __launch_bounds__(256, 2)
attn_kernel(const __nv_bfloat16* __restrict__ qHi, const __nv_bfloat16* __restrict__ qLo,
            const __nv_bfloat16* __restrict__ kHi, const __nv_bfloat16* __restrict__ kLo,
            const __nv_bfloat16* __restrict__ vHi, const __nv_bfloat16* __restrict__ vLo,
            __nv_bfloat16* __restrict__ oHi, __nv_bfloat16* __restrict__ oLo)
{
    extern __shared__ char smc[];
    const uint32_t smb = smem_u32(smc);
    const int tid  = threadIdx.x;
    const int wq   = tid >> 5;
    const int lane = tid & 31;
    const int g = lane >> 2, q = lane & 3;
    const int qb = blockIdx.x;
    const int b  = blockIdx.y >> 4, h = blockIdx.y & 15;

    const int rloc0 = wq * 16 + g;
    const int rg0   = qb * 128 + rloc0;
    const int rmin  = qb * 128 + wq * 16;

    {
        const size_t gq = (size_t)(b * TT + qb * 128) * EE + h * HD;
        #pragma unroll
        for (int i = 0; i < 8; i++) {
            const int f  = tid + (i << 8);
            const int op = f >> 10;
            const int e  = f & 1023;
            const int r  = e >> 3, c = e & 7;
            const __nv_bfloat16* src = (op ? qLo : qHi) + gq + (size_t)r * EE + c * 8;
            cp16(smb + op * 16384 + (r << 7) + ((c ^ (r & 7)) << 4), src);
        }
    }
    cp_commit();

    const int nk = 2 * qb + 2;

    auto ldkv = [&](int stg, int kb) {
        const int ktb = kb * 64;
        const size_t gk = (size_t)(b * TT + ktb) * EE + h * HD;
        const size_t gv = (size_t)(h * HD) * MT + b * TT + ktb;
        const uint32_t sb = smb + ATT_Q + stg * ATT_STG;
        #pragma unroll
        for (int i = 0; i < 8; i++) {
            const int f  = tid + (i << 8);
            const int op = f >> 9;
            const int e  = f & 511;
            const int r  = e >> 3, c = e & 7;
            const void* src;
            if (op == 0)      src = kHi + gk + (size_t)r * EE + c * 8;
            else if (op == 1) src = kLo + gk + (size_t)r * EE + c * 8;
            else if (op == 2) src = vHi + gv + (size_t)r * MT + c * 8;
            else              src = vLo + gv + (size_t)r * MT + c * 8;
            cp16(sb + op * 8192 + (r << 7) + ((c ^ (r & 7)) << 4), src);
        }
    };

    ldkv(0, 0); cp_commit();
    ldkv(1, 1); cp_commit();

    float o[8][4];
    #pragma unroll
    for (int nt = 0; nt < 8; nt++)
        #pragma unroll
        for (int r = 0; r < 4; r++) o[nt][r] = 0.0f;
    float m0 = -1e30f, m1 = -1e30f, l0 = 0.0f, l1 = 0.0f;

    for (int kb = 0; kb < nk; kb++) {
        const int p = kb & 1;
        cp_wait1();
        __syncthreads();
        const int ktb = kb * 64;
        if (ktb <= rmin + 15) {
            const char* qhp = smc;
            const char* qlp = smc + 16384;
            const char* kp  = smc + ATT_Q + p * ATT_STG;
            const char* klp = kp + 8192;
            const char* vhp = kp + 16384;
            const char* vlp = kp + 24576;
            const int r0 = rloc0, r1 = rloc0 + 8;

            float s[8][4];
            #pragma unroll
            for (int nt = 0; nt < 8; nt++)
                #pragma unroll
                for (int r = 0; r < 4; r++) s[nt][r] = 0.0f;
            #pragma unroll
            for (int s4 = 0; s4 < 4; s4++) {
                const int ch0 = 2 * s4, ch1 = ch0 + 1;
                uint32_t ah[4], al[4];
                ah[0] = *(const uint32_t*)(qhp + (r0 << 7) + ((ch0 ^ g) << 4) + 4 * q);
                ah[1] = *(const uint32_t*)(qhp + (r1 << 7) + ((ch0 ^ g) << 4) + 4 * q);
                ah[2] = *(const uint32_t*)(qhp + (r0 << 7) + ((ch1 ^ g) << 4) + 4 * q);
                ah[3] = *(const uint32_t*)(qhp + (r1 << 7) + ((ch1 ^ g) << 4) + 4 * q);
                al[0] = *(const uint32_t*)(qlp + (r0 << 7) + ((ch0 ^ g) << 4) + 4 * q);
                al[1] = *(const uint32_t*)(qlp + (r1 << 7) + ((ch0 ^ g) << 4) + 4 * q);
                al[2] = *(const uint32_t*)(qlp + (r0 << 7) + ((ch1 ^ g) << 4) + 4 * q);
                al[3] = *(const uint32_t*)(qlp + (r1 << 7) + ((ch1 ^ g) << 4) + 4 * q);
                #pragma unroll
                for (int nt = 0; nt < 8; nt++) {
                    const int rn = nt * 8 + g;
                    uint32_t bh[2], bl[2];
                    bh[0] = *(const uint32_t*)(kp  + (rn << 7) + ((ch0 ^ g) << 4) + 4 * q);
                    bh[1] = *(const uint32_t*)(kp  + (rn << 7) + ((ch1 ^ g) << 4) + 4 * q);
                    bl[0] = *(const uint32_t*)(klp + (rn << 7) + ((ch0 ^ g) << 4) + 4 * q);
                    bl[1] = *(const uint32_t*)(klp + (rn << 7) + ((ch1 ^ g) << 4) + 4 * q);
                    mma16816(s[nt], ah, bh);
                    mma16816(s[nt], ah, bl);
                    mma16816(s[nt], al, bh);
                }
            }

            if (ktb + 63 > rmin) {
                #pragma unroll
                for (int nt = 0; nt < 8; nt++) {
                    const int c0 = ktb + nt * 8 + 2 * q, c1 = c0 + 1;
                    if (c0 > rg0)     s[nt][0] = -1e30f;
                    if (c1 > rg0)     s[nt][1] = -1e30f;
                    if (c0 > rg0 + 8) s[nt][2] = -1e30f;
                    if (c1 > rg0 + 8) s[nt][3] = -1e30f;
                }
            }

            float mx0 = -1e30f, mx1 = -1e30f;
            #pragma unroll
            for (int nt = 0; nt < 8; nt++) {
                mx0 = fmaxf(mx0, fmaxf(s[nt][0], s[nt][1]));
                mx1 = fmaxf(mx1, fmaxf(s[nt][2], s[nt][3]));
            }
            mx0 = fmaxf(mx0, __shfl_xor_sync(0xffffffffu, mx0, 1));
            mx0 = fmaxf(mx0, __shfl_xor_sync(0xffffffffu, mx0, 2));
            mx1 = fmaxf(mx1, __shfl_xor_sync(0xffffffffu, mx1, 1));
            mx1 = fmaxf(mx1, __shfl_xor_sync(0xffffffffu, mx1, 2));
            const float mn0 = fmaxf(m0, mx0), mn1 = fmaxf(m1, mx1);
            const float a0 = fast_exp(m0 - mn0), a1 = fast_exp(m1 - mn1);
            m0 = mn0; m1 = mn1;
            float rs0 = 0.0f, rs1 = 0.0f;
            #pragma unroll
            for (int nt = 0; nt < 8; nt++) {
                s[nt][0] = fast_exp(s[nt][0] - mn0); rs0 += s[nt][0];
                s[nt][1] = fast_exp(s[nt][1] - mn0); rs0 += s[nt][1];
                s[nt][2] = fast_exp(s[nt][2] - mn1); rs1 += s[nt][2];
                s[nt][3] = fast_exp(s[nt][3] - mn1); rs1 += s[nt][3];
            }
            rs0 += __shfl_xor_sync(0xffffffffu, rs0, 1);
            rs0 += __shfl_xor_sync(0xffffffffu, rs0, 2);
            rs1 += __shfl_xor_sync(0xffffffffu, rs1, 1);
            rs1 += __shfl_xor_sync(0xffffffffu, rs1, 2);
            l0 = l0 * a0 + rs0;
            l1 = l1 * a1 + rs1;
            #pragma unroll
            for (int nt = 0; nt < 8; nt++) {
                o[nt][0] *= a0; o[nt][1] *= a0;
                o[nt][2] *= a1; o[nt][3] *= a1;
            }

            uint32_t ph[4][4], pl[4][4];
            #pragma unroll
            for (int kg = 0; kg < 4; kg++) {
                const int t0 = 2 * kg, t1 = 2 * kg + 1;
                split2(s[t0][0], s[t0][1], ph[kg][0], pl[kg][0]);
                split2(s[t0][2], s[t0][3], ph[kg][1], pl[kg][1]);
                split2(s[t1][0], s[t1][1], ph[kg][2], pl[kg][2]);
                split2(s[t1][2], s[t1][3], ph[kg][3], pl[kg][3]);
            }

            #pragma unroll
            for (int kg = 0; kg < 4; kg++) {
                const int ch0 = 2 * kg, ch1 = ch0 + 1;
                #pragma unroll
                for (int nt = 0; nt < 8; nt++) {
                    const int rd = nt * 8 + g;
                    uint32_t bh[2], bl[2];
                    bh[0] = *(const uint32_t*)(vhp + (rd << 7) + ((ch0 ^ g) << 4) + 4 * q);
                    bh[1] = *(const uint32_t*)(vhp + (rd << 7) + ((ch1 ^ g) << 4) + 4 * q);
                    bl[0] = *(const uint32_t*)(vlp + (rd << 7) + ((ch0 ^ g) << 4) + 4 * q);
                    bl[1] = *(const uint32_t*)(vlp + (rd << 7) + ((ch1 ^ g) << 4) + 4 * q);
                    mma16816(o[nt], ph[kg], bh);
                    mma16816(o[nt], ph[kg], bl);
                    mma16816(o[nt], pl[kg], bh);
                }
            }
        }
        __syncthreads();
        if (kb + 2 < nk) ldkv(p, kb + 2);
        cp_commit();
    }

    const float i0 = 1.0f / l0, i1 = 1.0f / l1;
    const size_t ob0 = (size_t)(b * TT + rg0) * EE + h * HD;
    const size_t ob1 = ob0 + 8 * EE;
    #pragma unroll
    for (int nt = 0; nt < 8; nt++) {
        const int cc = nt * 8 + 2 * q;
        uint32_t hi, lo;
        split2(o[nt][0] * i0, o[nt][1] * i0, hi, lo);
        *(uint32_t*)(oHi + ob0 + cc) = hi;
        *(uint32_t*)(oLo + ob0 + cc) = lo;
        split2(o[nt][2] * i1, o[nt][3] * i1, hi, lo);
        *(uint32_t*)(oHi + ob1 + cc) = hi;
        *(uint32_t*)(oLo + ob1 + cc) = lo;
    }
}

// ================= orchestration ==========================================
extern "C" void kernel_launch(void* const* d_in, const int* in_sizes, int n_in,
                              void* d_out, int out_size)
{
    const float* x    = (const float*)d_in[0];
    const float* Wq   = (const float*)d_in[1];
    const float* bq   = (const float*)d_in[2];
    const float* Wk   = (const float*)d_in[3];
    const float* bk   = (const float*)d_in[4];
    const float* Wv   = (const float*)d_in[5];
    const float* bv   = (const float*)d_in[6];
    const float* Wo   = (const float*)d_in[7];
    const float* bo   = (const float*)d_in[8];
    const float* W1   = (const float*)d_in[9];
    const float* b1   = (const float*)d_in[10];
    const float* W2   = (const float*)d_in[11];
    const float* b2   = (const float*)d_in[12];
    const float* ln1g = (const float*)d_in[13];
    const float* ln1b = (const float*)d_in[14];
    const float* ln2g = (const float*)d_in[15];
    const float* ln2b = (const float*)d_in[16];

    float* x1;
    __nv_bfloat16 *aHi, *aLo, *qHi, *qLo, *kHi, *kLo, *vtHi, *vtLo;
    __nv_bfloat16 *atHi, *atLo, *ffHi, *ffLo, *wHi, *wLo;
    cudaGetSymbolAddress((void**)&x1,   g_x1);
    cudaGetSymbolAddress((void**)&aHi,  g_aHi);
    cudaGetSymbolAddress((void**)&aLo,  g_aLo);
    cudaGetSymbolAddress((void**)&qHi,  g_qHi);
    cudaGetSymbolAddress((void**)&qLo,  g_qLo);
    cudaGetSymbolAddress((void**)&kHi,  g_kHi);
    cudaGetSymbolAddress((void**)&kLo,  g_kLo);
    cudaGetSymbolAddress((void**)&vtHi, g_vtHi);
    cudaGetSymbolAddress((void**)&vtLo, g_vtLo);
    cudaGetSymbolAddress((void**)&atHi, g_atHi);
    cudaGetSymbolAddress((void**)&atLo, g_atLo);
    cudaGetSymbolAddress((void**)&ffHi, g_ffHi);
    cudaGetSymbolAddress((void**)&ffLo, g_ffLo);
    cudaGetSymbolAddress((void**)&wHi,  g_wHi);
    cudaGetSymbolAddress((void**)&wLo,  g_wLo);

    cudaFuncSetAttribute(attn_kernel,
                         cudaFuncAttributeMaxDynamicSharedMemorySize, ATT_SMEM);
    cudaFuncSetAttribute(mma_gemm_kernel<0,0,1>,
                         cudaFuncAttributeMaxDynamicSharedMemorySize, GEMM_SMEM);
    cudaFuncSetAttribute(mma_gemm_kernel<0,0,2>,
                         cudaFuncAttributeMaxDynamicSharedMemorySize, GEMM_SMEM);
    cudaFuncSetAttribute(mma_gemm_kernel<0,1,0>,
                         cudaFuncAttributeMaxDynamicSharedMemorySize, GEMM_SMEM);
    cudaFuncSetAttribute(mma_gemm_kernel<1,0,1>,
                         cudaFuncAttributeMaxDynamicSharedMemorySize, GEMM_SMEM);

    const dim3 gE (EE  / 128, MT / 128);
    const dim3 gFF(FFD / 128, MT / 128);

    wsplit_kernel<<<12288, 256>>>(Wq, Wk, Wv, Wo, W1, W2, wHi, wLo);         // 0
    ln_kernel<<<MT, 256>>>(x, ln1g, ln1b, aHi, aLo);                         // 1
    mma_gemm_kernel<0,0,1><<<gE, 512, GEMM_SMEM>>>(aHi, aLo, wHi + WQ_OFF, wLo + WQ_OFF,
        bq, nullptr, nullptr, qHi, qLo, 0.125f, MT, EE, EE);                 // 2
    mma_gemm_kernel<0,0,1><<<gE, 512, GEMM_SMEM>>>(aHi, aLo, wHi + WK_OFF, wLo + WK_OFF,
        bk, nullptr, nullptr, kHi, kLo, 1.0f, MT, EE, EE);                   // 3
    mma_gemm_kernel<0,0,2><<<gE, 512, GEMM_SMEM>>>(aHi, aLo, wHi + WV_OFF, wLo + WV_OFF,
        bv, nullptr, nullptr, vtHi, vtLo, 1.0f, MT, EE, EE);                 // 4
    attn_kernel<<<dim3(TT / 128, BB * HH), 256, ATT_SMEM>>>(
        qHi, qLo, kHi, kLo, vtHi, vtLo, atHi, atLo);                         // 5
    mma_gemm_kernel<0,1,0><<<gE, 512, GEMM_SMEM>>>(atHi, atLo, wHi + WO_OFF, wLo + WO_OFF,
        bo, x, x1, nullptr, nullptr, 1.0f, MT, EE, EE);                      // 6
    ln_kernel<<<MT, 256>>>(x1, ln2g, ln2b, aHi, aLo);                        // 7
    mma_gemm_kernel<1,0,1><<<gFF, 512, GEMM_SMEM>>>(aHi, aLo, wHi + W1_OFF, wLo + W1_OFF,
        b1, nullptr, nullptr, ffHi, ffLo, 1.0f, MT, FFD, EE);                // 8
    mma_gemm_kernel<0,1,0><<<gE, 512, GEMM_SMEM>>>(ffHi, ffLo, wHi + W2_OFF, wLo + W2_OFF,
        b2, x1, (float*)d_out, nullptr, nullptr, 1.0f, MT, EE, FFD);         // 9
}

// round 8
// speedup vs baseline: 1.0322x; 1.0322x over previous
#include <cuda_runtime.h>
#include <cuda_bf16.h>
#include <cstdint>
#include <math.h>

// ---------------- problem constants ----------------
#define BB    2
#define TT    2048
#define EE    1024
#define HH    16
#define HD    64
#define FFD   4096
#define MT    (BB*TT)        // 4096 tokens

// ---------------- scratch (device globals) -------------------------------
__device__ __align__(16) float g_x1[MT*EE];

__device__ __align__(16) __nv_bfloat16 g_aHi [MT*EE];
__device__ __align__(16) __nv_bfloat16 g_aLo [MT*EE];
__device__ __align__(16) __nv_bfloat16 g_qHi [MT*EE];
__device__ __align__(16) __nv_bfloat16 g_qLo [MT*EE];
__device__ __align__(16) __nv_bfloat16 g_kHi [MT*EE];
__device__ __align__(16) __nv_bfloat16 g_kLo [MT*EE];
__device__ __align__(16) __nv_bfloat16 g_vtHi[EE*MT];
__device__ __align__(16) __nv_bfloat16 g_vtLo[EE*MT];
__device__ __align__(16) __nv_bfloat16 g_atHi[MT*EE];
__device__ __align__(16) __nv_bfloat16 g_atLo[MT*EE];
__device__ __align__(16) __nv_bfloat16 g_ffHi[MT*FFD];
__device__ __align__(16) __nv_bfloat16 g_ffLo[MT*FFD];
__device__ __align__(16) __nv_bfloat16 g_wHi [12582912];
__device__ __align__(16) __nv_bfloat16 g_wLo [12582912];

#define WQ_OFF 0
#define WK_OFF 1048576
#define WV_OFF 2097152
#define WO_OFF 3145728
#define W1_OFF 4194304
#define W2_OFF 8388608

// ================= helpers ================================================
__device__ __forceinline__ uint32_t smem_u32(const void* p) {
    uint32_t a;
    asm("{ .reg .u64 t; cvta.to.shared.u64 t, %1; cvt.u32.u64 %0, t; }"
        : "=r"(a) : "l"(p));
    return a;
}
__device__ __forceinline__ void cp16(uint32_t dst, const void* src) {
    asm volatile("cp.async.cg.shared.global [%0], [%1], 16;"
                 :: "r"(dst), "l"(src));
}
__device__ __forceinline__ void cp_commit() {
    asm volatile("cp.async.commit_group;" ::: "memory");
}
__device__ __forceinline__ void cp_wait1() {
    asm volatile("cp.async.wait_group 1;" ::: "memory");
}
__device__ __forceinline__ void mma16816(float* d, const uint32_t* a,
                                         const uint32_t* b) {
    asm volatile(
        "mma.sync.aligned.m16n8k16.row.col.f32.bf16.bf16.f32 "
        "{%0,%1,%2,%3}, {%4,%5,%6,%7}, {%8,%9}, {%0,%1,%2,%3};"
        : "+f"(d[0]), "+f"(d[1]), "+f"(d[2]), "+f"(d[3])
        : "r"(a[0]), "r"(a[1]), "r"(a[2]), "r"(a[3]), "r"(b[0]), "r"(b[1]));
}
__device__ __forceinline__ void ldsm4(uint32_t* r, uint32_t addr) {
    asm volatile("ldmatrix.sync.aligned.m8n8.x4.shared.b16 {%0,%1,%2,%3}, [%4];"
        : "=r"(r[0]), "=r"(r[1]), "=r"(r[2]), "=r"(r[3]) : "r"(addr));
}
// exp(x) for x <= 0, FMA-pipe only (no MUFU). rel err ~2e-6.
__device__ __forceinline__ float fast_exp(float x) {
    x = fmaxf(x, -80.0f);
    const float z = x * 1.4426950408889634f;
    const float t = z + 12582912.0f;
    const int  ik = __float_as_int(t) - 0x4B400000;
    const float f = z - (t - 12582912.0f);
    float p = 1.3333558146e-3f;
    p = fmaf(p, f, 9.6181291071e-3f);
    p = fmaf(p, f, 5.5504108664e-2f);
    p = fmaf(p, f, 2.4022650696e-1f);
    p = fmaf(p, f, 6.9314718056e-1f);
    p = fmaf(p, f, 1.0f);
    return __int_as_float(__float_as_int(p) + (ik << 23));
}
__device__ __forceinline__ void split2(float x, float y, uint32_t& hi, uint32_t& lo) {
    __nv_bfloat162 hp = __floats2bfloat162_rn(x, y);
    hi = *reinterpret_cast<uint32_t*>(&hp);
    __nv_bfloat162 lp = __floats2bfloat162_rn(x - __bfloat162float(hp.x),
                                              y - __bfloat162float(hp.y));
    lo = *reinterpret_cast<uint32_t*>(&lp);
}

// ================= LayerNorm -> bf16 hi/lo ===============================
__global__ void ln_kernel(const float* __restrict__ x,
                          const float* __restrict__ gw,
                          const float* __restrict__ bw,
                          __nv_bfloat16* __restrict__ hi,
                          __nv_bfloat16* __restrict__ lo)
{
    const int row = blockIdx.x;
    const int tid = threadIdx.x;
    const float4 xv = ((const float4*)(x + (size_t)row * EE))[tid];

    float s  = xv.x + xv.y + xv.z + xv.w;
    float ss = xv.x*xv.x + xv.y*xv.y + xv.z*xv.z + xv.w*xv.w;
    #pragma unroll
    for (int off = 16; off; off >>= 1) {
        s  += __shfl_xor_sync(0xffffffffu, s,  off);
        ss += __shfl_xor_sync(0xffffffffu, ss, off);
    }
    __shared__ float as_[8], bs_[8];
    __shared__ float mu_s, inv_s;
    if ((tid & 31) == 0) { as_[tid >> 5] = s; bs_[tid >> 5] = ss; }
    __syncthreads();
    if (tid == 0) {
        float S = 0.f, SS = 0.f;
        #pragma unroll
        for (int i = 0; i < 8; i++) { S += as_[i]; SS += bs_[i]; }
        const float mu  = S * (1.0f / EE);
        const float var = SS * (1.0f / EE) - mu * mu;
        mu_s  = mu;
        inv_s = rsqrtf(var + 1e-5f);
    }
    __syncthreads();
    const float mu = mu_s, inv = inv_s;
    const float4 gv = ((const float4*)gw)[tid];
    const float4 bv = ((const float4*)bw)[tid];
    const float o0 = (xv.x - mu) * inv * gv.x + bv.x;
    const float o1 = (xv.y - mu) * inv * gv.y + bv.y;
    const float o2 = (xv.z - mu) * inv * gv.z + bv.z;
    const float o3 = (xv.w - mu) * inv * gv.w + bv.w;
    uint32_t h01, l01, h23, l23;
    split2(o0, o1, h01, l01);
    split2(o2, o3, h23, l23);
    ((uint2*)(hi + (size_t)row * EE))[tid] = make_uint2(h01, h23);
    ((uint2*)(lo + (size_t)row * EE))[tid] = make_uint2(l01, l23);
}

// ================= fused weight split =====================================
__global__ void wsplit_kernel(const float* __restrict__ Wq, const float* __restrict__ Wk,
                              const float* __restrict__ Wv, const float* __restrict__ Wo,
                              const float* __restrict__ W1, const float* __restrict__ W2,
                              __nv_bfloat16* __restrict__ hi,
                              __nv_bfloat16* __restrict__ lo)
{
    const int i = blockIdx.x * blockDim.x + threadIdx.x;   // < 3145728
    const float* src;
    int si;
    if (i < (1 << 20)) {
        const int w = i >> 18;
        src = (w == 0) ? Wq : (w == 1) ? Wk : (w == 2) ? Wv : Wo;
        si = i & ((1 << 18) - 1);
    } else {
        const int j = i - (1 << 20);
        if (j < (1 << 20)) { src = W1; si = j; }
        else               { src = W2; si = j - (1 << 20); }
    }
    const float4 v = ((const float4*)src)[si];
    uint32_t h01, l01, h23, l23;
    split2(v.x, v.y, h01, l01);
    split2(v.z, v.w, h23, l23);
    ((uint2*)hi)[i] = make_uint2(h01, h23);
    ((uint2*)lo)[i] = make_uint2(l01, l23);
}

// ================= mma.sync GEMM (64x128 tile, 2 CTAs/SM) =================
// Y = A @ W^T (+bias)(+res)(relu)(*scale); OUT: 0 fp32, 1 bf16 split,
// 2 bf16 split transposed. CTA 64x128, BK=64, 8 warps (2x4), 2 stages.
#define A_OPB 8192                 // 64 rows x 128B
#define B_OPB 16384                // 128 rows x 128B
#define STB   (2*A_OPB + 2*B_OPB)  // 49152 per stage
#define GEMM_SMEM (2*STB)          // 98304 -> 2 CTAs/SM

__device__ __forceinline__ void gemm_ld_chunk(
    uint32_t smst,
    const __nv_bfloat16* __restrict__ Ahi, const __nv_bfloat16* __restrict__ Alo,
    const __nv_bfloat16* __restrict__ Bhi, const __nv_bfloat16* __restrict__ Blo,
    int bm, int bn, int K, int kc, int tid)
{
    #pragma unroll
    for (int i = 0; i < 12; i++) {
        const int f = tid + (i << 8);          // 0..3071
        const __nv_bfloat16* src;
        uint32_t dbase;
        int row, c, rb;
        if (f < 1024) {                        // A hi/lo: 2 x 512 lines
            const int op = f >> 9;
            const int e  = f & 511;
            row = e >> 3; c = e & 7; rb = bm;
            src = op ? Alo : Ahi;
            dbase = smst + op * A_OPB;
        } else {                               // B hi/lo: 2 x 1024 lines
            const int g2 = f - 1024;
            const int op = g2 >> 10;
            const int e  = g2 & 1023;
            row = e >> 3; c = e & 7; rb = bn;
            src = op ? Blo : Bhi;
            dbase = smst + 2 * A_OPB + op * B_OPB;
        }
        const void* g = src + (size_t)(rb + row) * K + kc * 64 + c * 8;
        cp16(dbase + (row << 7) + ((c ^ (row & 7)) << 4), g);
    }
}

template<int RELU, int HASRES, int OUT>
__global__ void __launch_bounds__(256, 2)
mma_gemm_kernel(const __nv_bfloat16* __restrict__ Ahi,
                const __nv_bfloat16* __restrict__ Alo,
                const __nv_bfloat16* __restrict__ Bhi,
                const __nv_bfloat16* __restrict__ Blo,
                const float* __restrict__ bias,
                const float* __restrict__ res,
                float* __restrict__ Y,
                __nv_bfloat16* __restrict__ Yhi,
                __nv_bfloat16* __restrict__ Ylo,
                float scale, int M, int N, int K)
{
    extern __shared__ char smc[];
    const uint32_t smb = smem_u32(smc);
    const int tid  = threadIdx.x;
    const int wid  = tid >> 5;
    const int lane = tid & 31;
    const int g = lane >> 2, q = lane & 3;
    const int wm = wid & 1, wn = wid >> 1;       // 2x4 warp grid
    const int bm = blockIdx.y << 6;              // 64-row tile
    const int bn = blockIdx.x << 7;              // 128-col tile

    // ldmatrix lane addressing
    const int lrow = lane & 7;
    const int a_ch = (lane >> 4) & 1;
    const int b_ch = (lane >> 3) & 1;
    uint32_t arow[2], brow[2];
    #pragma unroll
    for (int mi = 0; mi < 2; mi++)
        arow[mi] = (uint32_t)(wm * 32 + mi * 16 + ((lane >> 3) & 1) * 8 + lrow) << 7;
    #pragma unroll
    for (int nj = 0; nj < 2; nj++)
        brow[nj] = (uint32_t)(wn * 32 + nj * 16 + ((lane >> 4) & 1) * 8 + lrow) << 7;

    float acc[2][4][4];
    #pragma unroll
    for (int mi = 0; mi < 2; mi++)
        #pragma unroll
        for (int ni = 0; ni < 4; ni++)
            #pragma unroll
            for (int r = 0; r < 4; r++) acc[mi][ni][r] = 0.0f;

    const int nk = K >> 6;
    gemm_ld_chunk(smb,       Ahi, Alo, Bhi, Blo, bm, bn, K, 0, tid);
    cp_commit();
    gemm_ld_chunk(smb + STB, Ahi, Alo, Bhi, Blo, bm, bn, K, 1, tid);
    cp_commit();

    for (int c = 0; c < nk; c++) {
        const int p = c & 1;
        cp_wait1();
        __syncthreads();
        const uint32_t sb  = smb + p * STB;
        const uint32_t abh = sb;
        const uint32_t abl = sb + A_OPB;
        const uint32_t bbh = sb + 2 * A_OPB;
        const uint32_t bbl = sb + 2 * A_OPB + B_OPB;

        #pragma unroll
        for (int s = 0; s < 4; s++) {
            const uint32_t aswz = (uint32_t)(((2 * s + a_ch) ^ lrow) << 4);
            const uint32_t bswz = (uint32_t)(((2 * s + b_ch) ^ lrow) << 4);
            uint32_t ah[2][4], al[2][4], bh[2][4], bl[2][4];
            #pragma unroll
            for (int mi = 0; mi < 2; mi++) ldsm4(ah[mi], abh + arow[mi] + aswz);
            #pragma unroll
            for (int mi = 0; mi < 2; mi++) ldsm4(al[mi], abl + arow[mi] + aswz);
            #pragma unroll
            for (int nj = 0; nj < 2; nj++) ldsm4(bh[nj], bbh + brow[nj] + bswz);
            #pragma unroll
            for (int nj = 0; nj < 2; nj++) ldsm4(bl[nj], bbl + brow[nj] + bswz);
            #pragma unroll
            for (int mi = 0; mi < 2; mi++)
                #pragma unroll
                for (int ni = 0; ni < 4; ni++)
                    mma16816(acc[mi][ni], ah[mi], &bh[ni >> 1][(ni & 1) << 1]);
            #pragma unroll
            for (int mi = 0; mi < 2; mi++)
                #pragma unroll
                for (int ni = 0; ni < 4; ni++)
                    mma16816(acc[mi][ni], ah[mi], &bl[ni >> 1][(ni & 1) << 1]);
            #pragma unroll
            for (int mi = 0; mi < 2; mi++)
                #pragma unroll
                for (int ni = 0; ni < 4; ni++)
                    mma16816(acc[mi][ni], al[mi], &bh[ni >> 1][(ni & 1) << 1]);
        }
        __syncthreads();
        if (c + 2 < nk)
            gemm_ld_chunk(smb + p * STB, Ahi, Alo, Bhi, Blo, bm, bn, K, c + 2, tid);
        cp_commit();
    }

    // ---- epilogue ----
    #pragma unroll
    for (int mi = 0; mi < 2; mi++) {
        #pragma unroll
        for (int ni = 0; ni < 4; ni++) {
            const int row0 = bm + wm * 32 + mi * 16 + g;
            const int col  = bn + wn * 32 + ni * 8 + q * 2;
            const float b0 = bias[col], b1 = bias[col + 1];
            float v0 = acc[mi][ni][0] + b0;
            float v1 = acc[mi][ni][1] + b1;
            float v2 = acc[mi][ni][2] + b0;
            float v3 = acc[mi][ni][3] + b1;
            if (HASRES) {
                const float2 r0 = *(const float2*)&res[(size_t)row0 * N + col];
                const float2 r1 = *(const float2*)&res[(size_t)(row0 + 8) * N + col];
                v0 += r0.x; v1 += r0.y; v2 += r1.x; v3 += r1.y;
            }
            if (RELU) {
                v0 = fmaxf(v0, 0.f); v1 = fmaxf(v1, 0.f);
                v2 = fmaxf(v2, 0.f); v3 = fmaxf(v3, 0.f);
            }
            if (OUT == 0) {
                *(float2*)&Y[(size_t)row0 * N + col]       = make_float2(v0, v1);
                *(float2*)&Y[(size_t)(row0 + 8) * N + col] = make_float2(v2, v3);
            } else {
                v0 *= scale; v1 *= scale; v2 *= scale; v3 *= scale;
                if (OUT == 1) {
                    uint32_t h, l;
                    split2(v0, v1, h, l);
                    *(uint32_t*)&Yhi[(size_t)row0 * N + col] = h;
                    *(uint32_t*)&Ylo[(size_t)row0 * N + col] = l;
                    split2(v2, v3, h, l);
                    *(uint32_t*)&Yhi[(size_t)(row0 + 8) * N + col] = h;
                    *(uint32_t*)&Ylo[(size_t)(row0 + 8) * N + col] = l;
                } else {   // transposed split (for V): vt[col][row]
                    #pragma unroll
                    for (int e = 0; e < 4; e++) {
                        const float v = (e == 0) ? v0 : (e == 1) ? v1 : (e == 2) ? v2 : v3;
                        const int cc = col + (e & 1);
                        const int rr = row0 + ((e >> 1) << 3);
                        const __nv_bfloat16 hv = __float2bfloat16(v);
                        const __nv_bfloat16 lv = __float2bfloat16(v - __bfloat162float(hv));
                        Yhi[(size_t)cc * M + rr] = hv;
                        Ylo[(size_t)cc * M + rr] = lv;
                    }
                }
            }
        }
    }
}

// ================= mma flash attention (unchanged) ========================
#define ATT_Q   32768
#define ATT_STG 32768
#define ATT_SMEM (ATT_Q + 2*ATT_STG)   // 98304

__global__ void __launch_bounds__(256, 2)
attn_kernel(const __nv_bfloat16* __restrict__ qHi, const __nv_bfloat16* __restrict__ qLo,
            const __nv_bfloat16* __restrict__ kHi, const __nv_bfloat16* __restrict__ kLo,
            const __nv_bfloat16* __restrict__ vHi, const __nv_bfloat16* __restrict__ vLo,
            __nv_bfloat16* __restrict__ oHi, __nv_bfloat16* __restrict__ oLo)
{
    extern __shared__ char smc[];
    const uint32_t smb = smem_u32(smc);
    const int tid  = threadIdx.x;
    const int wq   = tid >> 5;
    const int lane = tid & 31;
    const int g = lane >> 2, q = lane & 3;
    const int qb = blockIdx.x;
    const int b  = blockIdx.y >> 4, h = blockIdx.y & 15;

    const int rloc0 = wq * 16 + g;
    const int rg0   = qb * 128 + rloc0;
    const int rmin  = qb * 128 + wq * 16;

    {
        const size_t gq = (size_t)(b * TT + qb * 128) * EE + h * HD;
        #pragma unroll
        for (int i = 0; i < 8; i++) {
            const int f  = tid + (i << 8);
            const int op = f >> 10;
            const int e  = f & 1023;
            const int r  = e >> 3, c = e & 7;
            const __nv_bfloat16* src = (op ? qLo : qHi) + gq + (size_t)r * EE + c * 8;
            cp16(smb + op * 16384 + (r << 7) + ((c ^ (r & 7)) << 4), src);
        }
    }
    cp_commit();

    const int nk = 2 * qb + 2;

    auto ldkv = [&](int stg, int kb) {
        const int ktb = kb * 64;
        const size_t gk = (size_t)(b * TT + ktb) * EE + h * HD;
        const size_t gv = (size_t)(h * HD) * MT + b * TT + ktb;
        const uint32_t sb = smb + ATT_Q + stg * ATT_STG;
        #pragma unroll
        for (int i = 0; i < 8; i++) {
            const int f  = tid + (i << 8);
            const int op = f >> 9;
            const int e  = f & 511;
            const int r  = e >> 3, c = e & 7;
            const void* src;
            if (op == 0)      src = kHi + gk + (size_t)r * EE + c * 8;
            else if (op == 1) src = kLo + gk + (size_t)r * EE + c * 8;
            else if (op == 2) src = vHi + gv + (size_t)r * MT + c * 8;
            else              src = vLo + gv + (size_t)r * MT + c * 8;
            cp16(sb + op * 8192 + (r << 7) + ((c ^ (r & 7)) << 4), src);
        }
    };

    ldkv(0, 0); cp_commit();
    ldkv(1, 1); cp_commit();

    float o[8][4];
    #pragma unroll
    for (int nt = 0; nt < 8; nt++)
        #pragma unroll
        for (int r = 0; r < 4; r++) o[nt][r] = 0.0f;
    float m0 = -1e30f, m1 = -1e30f, l0 = 0.0f, l1 = 0.0f;

    for (int kb = 0; kb < nk; kb++) {
        const int p = kb & 1;
        cp_wait1();
        __syncthreads();
        const int ktb = kb * 64;
        if (ktb <= rmin + 15) {
            const char* qhp = smc;
            const char* qlp = smc + 16384;
            const char* kp  = smc + ATT_Q + p * ATT_STG;
            const char* klp = kp + 8192;
            const char* vhp = kp + 16384;
            const char* vlp = kp + 24576;
            const int r0 = rloc0, r1 = rloc0 + 8;

            float s[8][4];
            #pragma unroll
            for (int nt = 0; nt < 8; nt++)
                #pragma unroll
                for (int r = 0; r < 4; r++) s[nt][r] = 0.0f;
            #pragma unroll
            for (int s4 = 0; s4 < 4; s4++) {
                const int ch0 = 2 * s4, ch1 = ch0 + 1;
                uint32_t ah[4], al[4];
                ah[0] = *(const uint32_t*)(qhp + (r0 << 7) + ((ch0 ^ g) << 4) + 4 * q);
                ah[1] = *(const uint32_t*)(qhp + (r1 << 7) + ((ch0 ^ g) << 4) + 4 * q);
                ah[2] = *(const uint32_t*)(qhp + (r0 << 7) + ((ch1 ^ g) << 4) + 4 * q);
                ah[3] = *(const uint32_t*)(qhp + (r1 << 7) + ((ch1 ^ g) << 4) + 4 * q);
                al[0] = *(const uint32_t*)(qlp + (r0 << 7) + ((ch0 ^ g) << 4) + 4 * q);
                al[1] = *(const uint32_t*)(qlp + (r1 << 7) + ((ch0 ^ g) << 4) + 4 * q);
                al[2] = *(const uint32_t*)(qlp + (r0 << 7) + ((ch1 ^ g) << 4) + 4 * q);
                al[3] = *(const uint32_t*)(qlp + (r1 << 7) + ((ch1 ^ g) << 4) + 4 * q);
                #pragma unroll
                for (int nt = 0; nt < 8; nt++) {
                    const int rn = nt * 8 + g;
                    uint32_t bh[2], bl[2];
                    bh[0] = *(const uint32_t*)(kp  + (rn << 7) + ((ch0 ^ g) << 4) + 4 * q);
                    bh[1] = *(const uint32_t*)(kp  + (rn << 7) + ((ch1 ^ g) << 4) + 4 * q);
                    bl[0] = *(const uint32_t*)(klp + (rn << 7) + ((ch0 ^ g) << 4) + 4 * q);
                    bl[1] = *(const uint32_t*)(klp + (rn << 7) + ((ch1 ^ g) << 4) + 4 * q);
                    mma16816(s[nt], ah, bh);
                    mma16816(s[nt], ah, bl);
                    mma16816(s[nt], al, bh);
                }
            }

            if (ktb + 63 > rmin) {
                #pragma unroll
                for (int nt = 0; nt < 8; nt++) {
                    const int c0 = ktb + nt * 8 + 2 * q, c1 = c0 + 1;
                    if (c0 > rg0)     s[nt][0] = -1e30f;
                    if (c1 > rg0)     s[nt][1] = -1e30f;
                    if (c0 > rg0 + 8) s[nt][2] = -1e30f;
                    if (c1 > rg0 + 8) s[nt][3] = -1e30f;
                }
            }

            float mx0 = -1e30f, mx1 = -1e30f;
            #pragma unroll
            for (int nt = 0; nt < 8; nt++) {
                mx0 = fmaxf(mx0, fmaxf(s[nt][0], s[nt][1]));
                mx1 = fmaxf(mx1, fmaxf(s[nt][2], s[nt][3]));
            }
            mx0 = fmaxf(mx0, __shfl_xor_sync(0xffffffffu, mx0, 1));
            mx0 = fmaxf(mx0, __shfl_xor_sync(0xffffffffu, mx0, 2));
            mx1 = fmaxf(mx1, __shfl_xor_sync(0xffffffffu, mx1, 1));
            mx1 = fmaxf(mx1, __shfl_xor_sync(0xffffffffu, mx1, 2));
            const float mn0 = fmaxf(m0, mx0), mn1 = fmaxf(m1, mx1);
            const float a0 = fast_exp(m0 - mn0), a1 = fast_exp(m1 - mn1);
            m0 = mn0; m1 = mn1;
            float rs0 = 0.0f, rs1 = 0.0f;
            #pragma unroll
            for (int nt = 0; nt < 8; nt++) {
                s[nt][0] = fast_exp(s[nt][0] - mn0); rs0 += s[nt][0];
                s[nt][1] = fast_exp(s[nt][1] - mn0); rs0 += s[nt][1];
                s[nt][2] = fast_exp(s[nt][2] - mn1); rs1 += s[nt][2];
                s[nt][3] = fast_exp(s[nt][3] - mn1); rs1 += s[nt][3];
            }
            rs0 += __shfl_xor_sync(0xffffffffu, rs0, 1);
            rs0 += __shfl_xor_sync(0xffffffffu, rs0, 2);
            rs1 += __shfl_xor_sync(0xffffffffu, rs1, 1);
            rs1 += __shfl_xor_sync(0xffffffffu, rs1, 2);
            l0 = l0 * a0 + rs0;
            l1 = l1 * a1 + rs1;
            #pragma unroll
            for (int nt = 0; nt < 8; nt++) {
                o[nt][0] *= a0; o[nt][1] *= a0;
                o[nt][2] *= a1; o[nt][3] *= a1;
            }

            uint32_t ph[4][4], pl[4][4];
            #pragma unroll
            for (int kg = 0; kg < 4; kg++) {
                const int t0 = 2 * kg, t1 = 2 * kg + 1;
                split2(s[t0][0], s[t0][1], ph[kg][0], pl[kg][0]);
                split2(s[t0][2], s[t0][3], ph[kg][1], pl[kg][1]);
                split2(s[t1][0], s[t1][1], ph[kg][2], pl[kg][2]);
                split2(s[t1][2], s[t1][3], ph[kg][3], pl[kg][3]);
            }

            #pragma unroll
            for (int kg = 0; kg < 4; kg++) {
                const int ch0 = 2 * kg, ch1 = ch0 + 1;
                #pragma unroll
                for (int nt = 0; nt < 8; nt++) {
                    const int rd = nt * 8 + g;
                    uint32_t bh[2], bl[2];
                    bh[0] = *(const uint32_t*)(vhp + (rd << 7) + ((ch0 ^ g) << 4) + 4 * q);
                    bh[1] = *(const uint32_t*)(vhp + (rd << 7) + ((ch1 ^ g) << 4) + 4 * q);
                    bl[0] = *(const uint32_t*)(vlp + (rd << 7) + ((ch0 ^ g) << 4) + 4 * q);
                    bl[1] = *(const uint32_t*)(vlp + (rd << 7) + ((ch1 ^ g) << 4) + 4 * q);
                    mma16816(o[nt], ph[kg], bh);
                    mma16816(o[nt], ph[kg], bl);
                    mma16816(o[nt], pl[kg], bh);
                }
            }
        }
        __syncthreads();
        if (kb + 2 < nk) ldkv(p, kb + 2);
        cp_commit();
    }

    const float i0 = 1.0f / l0, i1 = 1.0f / l1;
    const size_t ob0 = (size_t)(b * TT + rg0) * EE + h * HD;
    const size_t ob1 = ob0 + 8 * EE;
    #pragma unroll
    for (int nt = 0; nt < 8; nt++) {
        const int cc = nt * 8 + 2 * q;
        uint32_t hi, lo;
        split2(o[nt][0] * i0, o[nt][1] * i0, hi, lo);
        *(uint32_t*)(oHi + ob0 + cc) = hi;
        *(uint32_t*)(oLo + ob0 + cc) = lo;
        split2(o[nt][2] * i1, o[nt][3] * i1, hi, lo);
        *(uint32_t*)(oHi + ob1 + cc) = hi;
        *(uint32_t*)(oLo + ob1 + cc) = lo;
    }
}

// ================= orchestration ==========================================
extern "C" void kernel_launch(void* const* d_in, const int* in_sizes, int n_in,
                              void* d_out, int out_size)
{
    const float* x    = (const float*)d_in[0];
    const float* Wq   = (const float*)d_in[1];
    const float* bq   = (const float*)d_in[2];
    const float* Wk   = (const float*)d_in[3];
    const float* bk   = (const float*)d_in[4];
    const float* Wv   = (const float*)d_in[5];
    const float* bv   = (const float*)d_in[6];
    const float* Wo   = (const float*)d_in[7];
    const float* bo   = (const float*)d_in[8];
    const float* W1   = (const float*)d_in[9];
    const float* b1   = (const float*)d_in[10];
    const float* W2   = (const float*)d_in[11];
    const float* b2   = (const float*)d_in[12];
    const float* ln1g = (const float*)d_in[13];
    const float* ln1b = (const float*)d_in[14];
    const float* ln2g = (const float*)d_in[15];
    const float* ln2b = (const float*)d_in[16];

    float* x1;
    __nv_bfloat16 *aHi, *aLo, *qHi, *qLo, *kHi, *kLo, *vtHi, *vtLo;
    __nv_bfloat16 *atHi, *atLo, *ffHi, *ffLo, *wHi, *wLo;
    cudaGetSymbolAddress((void**)&x1,   g_x1);
    cudaGetSymbolAddress((void**)&aHi,  g_aHi);
    cudaGetSymbolAddress((void**)&aLo,  g_aLo);
    cudaGetSymbolAddress((void**)&qHi,  g_qHi);
    cudaGetSymbolAddress((void**)&qLo,  g_qLo);
    cudaGetSymbolAddress((void**)&kHi,  g_kHi);
    cudaGetSymbolAddress((void**)&kLo,  g_kLo);
    cudaGetSymbolAddress((void**)&vtHi, g_vtHi);
    cudaGetSymbolAddress((void**)&vtLo, g_vtLo);
    cudaGetSymbolAddress((void**)&atHi, g_atHi);
    cudaGetSymbolAddress((void**)&atLo, g_atLo);
    cudaGetSymbolAddress((void**)&ffHi, g_ffHi);
    cudaGetSymbolAddress((void**)&ffLo, g_ffLo);
    cudaGetSymbolAddress((void**)&wHi,  g_wHi);
    cudaGetSymbolAddress((void**)&wLo,  g_wLo);

    cudaFuncSetAttribute(attn_kernel,
                         cudaFuncAttributeMaxDynamicSharedMemorySize, ATT_SMEM);
    cudaFuncSetAttribute(mma_gemm_kernel<0,0,1>,
                         cudaFuncAttributeMaxDynamicSharedMemorySize, GEMM_SMEM);
    cudaFuncSetAttribute(mma_gemm_kernel<0,0,2>,
                         cudaFuncAttributeMaxDynamicSharedMemorySize, GEMM_SMEM);
    cudaFuncSetAttribute(mma_gemm_kernel<0,1,0>,
                         cudaFuncAttributeMaxDynamicSharedMemorySize, GEMM_SMEM);
    cudaFuncSetAttribute(mma_gemm_kernel<1,0,1>,
                         cudaFuncAttributeMaxDynamicSharedMemorySize, GEMM_SMEM);

    const dim3 gE (EE  / 128, MT / 64);   // (8, 64)
    const dim3 gFF(FFD / 128, MT / 64);   // (32, 64)

    wsplit_kernel<<<12288, 256>>>(Wq, Wk, Wv, Wo, W1, W2, wHi, wLo);         // 0
    ln_kernel<<<MT, 256>>>(x, ln1g, ln1b, aHi, aLo);                         // 1
    mma_gemm_kernel<0,0,1><<<gE, 256, GEMM_SMEM>>>(aHi, aLo, wHi + WQ_OFF, wLo + WQ_OFF,
        bq, nullptr, nullptr, qHi, qLo, 0.125f, MT, EE, EE);                 // 2
    mma_gemm_kernel<0,0,1><<<gE, 256, GEMM_SMEM>>>(aHi, aLo, wHi + WK_OFF, wLo + WK_OFF,
        bk, nullptr, nullptr, kHi, kLo, 1.0f, MT, EE, EE);                   // 3
    mma_gemm_kernel<0,0,2><<<gE, 256, GEMM_SMEM>>>(aHi, aLo, wHi + WV_OFF, wLo + WV_OFF,
        bv, nullptr, nullptr, vtHi, vtLo, 1.0f, MT, EE, EE);                 // 4
    attn_kernel<<<dim3(TT / 128, BB * HH), 256, ATT_SMEM>>>(
        qHi, qLo, kHi, kLo, vtHi, vtLo, atHi, atLo);                         // 5
    mma_gemm_kernel<0,1,0><<<gE, 256, GEMM_SMEM>>>(atHi, atLo, wHi + WO_OFF, wLo + WO_OFF,
        bo, x, x1, nullptr, nullptr, 1.0f, MT, EE, EE);                      // 6
    ln_kernel<<<MT, 256>>>(x1, ln2g, ln2b, aHi, aLo);                        // 7
    mma_gemm_kernel<1,0,1><<<gFF, 256, GEMM_SMEM>>>(aHi, aLo, wHi + W1_OFF, wLo + W1_OFF,
        b1, nullptr, nullptr, ffHi, ffLo, 1.0f, MT, FFD, EE);                // 8
    mma_gemm_kernel<0,1,0><<<gE, 256, GEMM_SMEM>>>(ffHi, ffLo, wHi + W2_OFF, wLo + W2_OFF,
        b2, x1, (float*)d_out, nullptr, nullptr, 1.0f, MT, EE, FFD);         // 9
}